// round 1
// baseline (speedup 1.0000x reference)
#include <cuda_runtime.h>

#define H  24
#define IN 8
#define THREADS 256

// Constant block layout (filled by prologue, read by main kernel)
#define NC       512
#define PD_OFF   0      // dt * P              [24*8]
#define PZ_OFF   192    // sp(e_p) * sp(P)     [24*8]
#define A1_OFF   384    // K@r + b_z           [24]
#define C0_OFF   408    // v0 + dt*(W@(UXr)+b_v) [24]
#define ZM_OFF   432    // -dt * v0            [24]
#define FLAG_OFF 456    // any(v0 != 0) ? 1 : 0

__device__ float g_consts[NC];

__device__ __forceinline__ float sp_f(float x) {
    // softplus, numerically stable: max(x,0) + log1p(exp(-|x|))
    return fmaxf(x, 0.0f) + log1pf(expf(-fabsf(x)));
}
__device__ __forceinline__ float sig_f(float x) {
    return 1.0f / (1.0f + expf(-x));
}

// ---------------------------------------------------------------------------
// Prologue: all batch-invariant math (runs once, 1 block, negligible cost)
// ---------------------------------------------------------------------------
__global__ void cb_rnn_prologue(const float* __restrict__ W,  const float* __restrict__ P,
                                const float* __restrict__ bv, const float* __restrict__ bz,
                                const float* __restrict__ e,  const float* __restrict__ ep,
                                const float* __restrict__ cx, const float* __restrict__ cu,
                                const float* __restrict__ cU, const float* __restrict__ v0,
                                const float* __restrict__ X0, const float* __restrict__ U0) {
    __shared__ float s_r[H], s_w[H];
    const int t = threadIdx.x;
    const float ke = sp_f(e[0]);
    const float pe = sp_f(ep[0]);

    if (t < H) {
        float rv = sig_f(v0[t]);
        s_r[t] = rv;
        // depression X
        float zx = 0.001f + 0.099f * sig_f(cx[t]);
        float X  = zx + (1.0f - zx) * X0[t] - U0[t] * X0[t] * rv;   // delta_t = 1
        // facilitation U with clamp [Ucap, 1]
        float zu   = 0.001f + 0.099f * sig_f(cu[t]);
        float Ucap = 0.9f * sig_f(cU[t]);
        float U = Ucap * zu + (1.0f - zu) * U0[t] + Ucap * (1.0f - U0[t]) * rv;
        U = fminf(fmaxf(U, Ucap), 1.0f);
        s_w[t] = U * X * rv;
    }
    __syncthreads();

    if (t < H) {
        float kr = 0.0f, wur = 0.0f;
        #pragma unroll
        for (int j = 0; j < H; ++j) {
            float Wv = W[t * H + j];
            kr  += sp_f(Wv) * s_r[j];
            wur += Wv * s_w[j];
        }
        g_consts[A1_OFF + t] = ke * kr + bz[t];
        g_consts[C0_OFF + t] = v0[t] + 0.1f * (wur + bv[t]);
        g_consts[ZM_OFF + t] = -0.1f * v0[t];
        #pragma unroll
        for (int i = 0; i < IN; ++i) {
            float Pv = P[t * IN + i];
            g_consts[PD_OFF + t * IN + i] = 0.1f * Pv;
            g_consts[PZ_OFF + t * IN + i] = pe * sp_f(Pv);
        }
    }
    if (t == 0) {
        int f = 0;
        for (int j = 0; j < H; ++j) f |= (v0[j] != 0.0f);
        g_consts[FLAG_OFF] = (float)f;
        // pad rest (never read, but keep deterministic)
        for (int j = FLAG_OFF + 1; j < NC; ++j) g_consts[j] = 0.0f;
    }
}

// ---------------------------------------------------------------------------
// Main: per-batch v[h,b] = c0[h] + (dt*P)[h,:]·x[:,b]  ( - dt*sig(...)·v0[h] )
// Output staged via padded smem for fully coalesced global stores.
// ---------------------------------------------------------------------------
__global__ void __launch_bounds__(THREADS)
cb_rnn_main(const float* __restrict__ x, float* __restrict__ out, int B) {
    __shared__ float sc[NC];
    __shared__ float so[THREADS * 25];   // pad 24 -> 25 (coprime with 32 banks)

    const int t = threadIdx.x;
    #pragma unroll
    for (int i = 0; i < NC / THREADS; ++i)
        sc[t + i * THREADS] = g_consts[t + i * THREADS];
    __syncthreads();

    const int b = blockIdx.x * THREADS + t;
    const bool inb = (b < B);

    float xv[IN];
    #pragma unroll
    for (int i = 0; i < IN; ++i)
        xv[i] = inb ? __ldcs(x + (size_t)i * (size_t)B + b) : 0.0f;

    if (sc[FLAG_OFF] == 0.0f) {
        // v0 == 0 everywhere: (1 - z_t)*v0 == 0 exactly, skip sigmoid path
        #pragma unroll
        for (int h = 0; h < H; ++h) {
            float v = sc[C0_OFF + h];
            #pragma unroll
            for (int i = 0; i < IN; ++i)
                v = fmaf(sc[PD_OFF + h * IN + i], xv[i], v);
            so[t * 25 + h] = v;
        }
    } else {
        #pragma unroll
        for (int h = 0; h < H; ++h) {
            float v = sc[C0_OFF + h];
            float a = sc[A1_OFF + h];
            #pragma unroll
            for (int i = 0; i < IN; ++i) {
                v = fmaf(sc[PD_OFF + h * IN + i], xv[i], v);
                a = fmaf(sc[PZ_OFF + h * IN + i], xv[i], a);
            }
            float s = 1.0f / (1.0f + __expf(-a));   // z_t/dt
            v = fmaf(s, sc[ZM_OFF + h], v);         // v += sig * (-dt*v0[h])
            so[t * 25 + h] = v;
        }
    }
    __syncthreads();

    // Coalesced writeout: block owns flat out range [blockIdx*6144, +6144)
    const size_t base  = (size_t)blockIdx.x * (THREADS * H);
    const size_t total = (size_t)B * H;
    #pragma unroll
    for (int k = 0; k < H; ++k) {
        unsigned f = (unsigned)(k * THREADS + t);
        size_t o = base + f;
        if (o < total) {
            unsigned q = f / 24u;            // compiler emits magic-multiply
            unsigned h = f - q * 24u;
            out[o] = so[q * 25 + h];
        }
    }
}

// ---------------------------------------------------------------------------
extern "C" void kernel_launch(void* const* d_in, const int* in_sizes, int n_in,
                              void* d_out, int out_size) {
    const float* x  = (const float*)d_in[0];
    const float* W  = (const float*)d_in[1];
    const float* P  = (const float*)d_in[2];
    const float* bv = (const float*)d_in[3];
    const float* bz = (const float*)d_in[4];
    const float* e  = (const float*)d_in[5];
    const float* ep = (const float*)d_in[6];
    const float* cx = (const float*)d_in[7];
    const float* cu = (const float*)d_in[8];
    const float* cU = (const float*)d_in[9];
    const float* v0 = (const float*)d_in[10];
    const float* X0 = (const float*)d_in[11];
    const float* U0 = (const float*)d_in[12];

    const int B = in_sizes[0] / IN;

    cb_rnn_prologue<<<1, 32>>>(W, P, bv, bz, e, ep, cx, cu, cU, v0, X0, U0);

    const int grid = (B + THREADS - 1) / THREADS;
    cb_rnn_main<<<grid, THREADS>>>(x, (float*)d_out, B);
}

// round 2
// speedup vs baseline: 1.0015x; 1.0015x over previous
#include <cuda_runtime.h>

#define TPB     256
#define SPAIR   50                       // word stride per row-pair (conflict-free: 50t mod 32 distinct)
#define NPAIRS  512                      // 1024 rows per block
#define PS_WORDS (NPAIRS * SPAIR)        // 25600 floats
#define CROW    20                       // floats per coef row: 8 dup pairs (16) + dup bias (2) + pad (2)
#define PD_BASE  PS_WORDS                // dt*P dup pairs + c0 dup      (24*20)
#define PZ_BASE  (PD_BASE + 24*CROW)     // pe*sp(P) dup pairs + a1 dup  (24*20)
#define ZM_BASE  (PZ_BASE + 24*CROW)     // -dt*v0 dup pairs             (48)
#define FLAG_OFS (ZM_BASE + 48)
#define SCR_BASE (FLAG_OFS + 4)          // r 24, w 24, pkr 192, pwr 192
#define SMEM_FLOATS (SCR_BASE + 432)
#define SMEM_BYTES  (SMEM_FLOATS * 4)    // 108,176 B -> 2 blocks/SM

typedef unsigned long long u64;

__device__ __forceinline__ float sp_f(float x) {            // accurate softplus
    return fmaxf(x, 0.0f) + log1pf(expf(-fabsf(x)));
}
__device__ __forceinline__ float sig_f(float x) {
    return 1.0f / (1.0f + expf(-x));
}
__device__ __forceinline__ u64 fma2(u64 a, u64 b, u64 c) {  // packed f32x2 FMA
    u64 d;
    asm("fma.rn.f32x2 %0, %1, %2, %3;" : "=l"(d) : "l"(a), "l"(b), "l"(c));
    return d;
}
__device__ __forceinline__ float2 u2f(u64 v) {
    float2 r;
    asm("mov.b64 {%0, %1}, %2;" : "=f"(r.x), "=f"(r.y) : "l"(v));
    return r;
}
__device__ __forceinline__ u64 f2u(float a, float b) {
    u64 v;
    asm("mov.b64 %0, {%1, %2};" : "=l"(v) : "f"(a), "f"(b));
    return v;
}

// Load two consecutive batch columns as a packed pair, with tail/alignment guards.
__device__ __forceinline__ u64 ldpair(const float* __restrict__ p, int row, int B, bool even) {
    if (even && (row + 1 < B))
        return __ldcs((const u64*)(p + row));
    float lo = (row     < B) ? __ldcs(p + row)     : 0.0f;
    float hi = (row + 1 < B) ? __ldcs(p + row + 1) : 0.0f;
    return f2u(lo, hi);
}

// ---------------------------------------------------------------------------
// Per-block prologue: all batch-invariant math, distributed over the block.
// ---------------------------------------------------------------------------
__device__ __forceinline__ void block_prologue(
    float* dynsm,
    const float* __restrict__ W,  const float* __restrict__ P,
    const float* __restrict__ bv, const float* __restrict__ bz,
    const float* __restrict__ e,  const float* __restrict__ ep,
    const float* __restrict__ cx, const float* __restrict__ cu,
    const float* __restrict__ cU, const float* __restrict__ v0,
    const float* __restrict__ X0, const float* __restrict__ U0)
{
    const int t = threadIdx.x;
    float* rS  = dynsm + SCR_BASE;        // 24
    float* wS  = rS + 24;                 // 24
    float* pkr = wS + 24;                 // 24*8
    float* pwr = pkr + 192;               // 24*8

    if (t < 24) {
        float v0v = v0[t];
        float rv  = sig_f(v0v);
        rS[t] = rv;
        float zx = 0.001f + 0.099f * sig_f(cx[t]);
        float X  = zx + (1.0f - zx) * X0[t] - U0[t] * X0[t] * rv;
        float zu   = 0.001f + 0.099f * sig_f(cu[t]);
        float Ucap = 0.9f * sig_f(cU[t]);
        float U = Ucap * zu + (1.0f - zu) * U0[t] + Ucap * (1.0f - U0[t]) * rv;
        U = fminf(fmaxf(U, Ucap), 1.0f);
        wS[t] = U * X * rv;
        float zm = -0.1f * v0v;
        dynsm[ZM_BASE + 2 * t]     = zm;
        dynsm[ZM_BASE + 2 * t + 1] = zm;
    }
    if (t == 0) {
        float f = 0.0f;
        #pragma unroll
        for (int j = 0; j < 24; ++j)
            if (v0[j] != 0.0f) f = 1.0f;
        dynsm[FLAG_OFS] = f;
    }
    __syncthreads();

    if (t < 192) {
        const int row = t >> 3;          // 0..23
        const int q   = t & 7;           // 0..7
        float kr = 0.0f, wur = 0.0f;
        #pragma unroll
        for (int jj = 0; jj < 3; ++jj) {
            int j = q * 3 + jj;
            float Wv = W[row * 24 + j];
            kr  += sp_f(Wv) * rS[j];
            wur += Wv * wS[j];
        }
        pkr[row * 8 + q] = kr;
        pwr[row * 8 + q] = wur;
        // P entry: h=row, i=q  (P layout (H, IN) row-major)
        float pe = sp_f(ep[0]);
        float Pv = P[row * 8 + q];
        float pd = 0.1f * Pv;
        float pz = pe * sp_f(Pv);
        int hb = PD_BASE + row * CROW + 2 * q;
        dynsm[hb] = pd;  dynsm[hb + 1] = pd;
        int zb = PZ_BASE + row * CROW + 2 * q;
        dynsm[zb] = pz;  dynsm[zb + 1] = pz;
    }
    __syncthreads();

    if (t < 24) {
        float kr = 0.0f, wur = 0.0f;
        #pragma unroll
        for (int k = 0; k < 8; ++k) { kr += pkr[t * 8 + k]; wur += pwr[t * 8 + k]; }
        float ke = sp_f(e[0]);
        float a1 = ke * kr + bz[t];
        float c0 = v0[t] + 0.1f * (wur + bv[t]);
        dynsm[PZ_BASE + t * CROW + 16] = a1;  dynsm[PZ_BASE + t * CROW + 17] = a1;
        dynsm[PD_BASE + t * CROW + 16] = c0;  dynsm[PD_BASE + t * CROW + 17] = c0;
    }
    __syncthreads();
}

// ---------------------------------------------------------------------------
// Fused kernel: block covers 1024 batch rows; thread owns row-pairs t and 256+t.
// ---------------------------------------------------------------------------
__global__ void __launch_bounds__(TPB)
cb_fused(const float* __restrict__ x, float* __restrict__ out, int B,
         const float* __restrict__ W,  const float* __restrict__ P,
         const float* __restrict__ bv, const float* __restrict__ bz,
         const float* __restrict__ e,  const float* __restrict__ ep,
         const float* __restrict__ cx, const float* __restrict__ cu,
         const float* __restrict__ cU, const float* __restrict__ v0,
         const float* __restrict__ X0, const float* __restrict__ U0)
{
    extern __shared__ float dynsm[];
    const int t = threadIdx.x;
    const int rowA = blockIdx.x * 1024 + 2 * t;
    const int rowB = rowA + 512;
    const bool even = (B & 1) == 0;

    // Issue x loads first so they overlap the prologue.
    u64 xa[8], xb[8];
    #pragma unroll
    for (int i = 0; i < 8; ++i) {
        const float* xi = x + i * B;
        xa[i] = ldpair(xi, rowA, B, even);
        xb[i] = ldpair(xi, rowB, B, even);
    }

    block_prologue(dynsm, W, P, bv, bz, e, ep, cx, cu, cU, v0, X0, U0);

    const float flagv = dynsm[FLAG_OFS];

    #pragma unroll
    for (int h = 0; h < 24; ++h) {
        const float* rowp = dynsm + PD_BASE + h * CROW;
        ulonglong2 q0 = *(const ulonglong2*)(rowp);
        ulonglong2 q1 = *(const ulonglong2*)(rowp + 4);
        ulonglong2 q2 = *(const ulonglong2*)(rowp + 8);
        ulonglong2 q3 = *(const ulonglong2*)(rowp + 12);
        u64 c0d = *(const u64*)(rowp + 16);

        u64 vA = fma2(q0.x, xa[0], c0d);
        vA = fma2(q0.y, xa[1], vA);
        vA = fma2(q1.x, xa[2], vA);
        vA = fma2(q1.y, xa[3], vA);
        vA = fma2(q2.x, xa[4], vA);
        vA = fma2(q2.y, xa[5], vA);
        vA = fma2(q3.x, xa[6], vA);
        vA = fma2(q3.y, xa[7], vA);

        u64 vB = fma2(q0.x, xb[0], c0d);
        vB = fma2(q0.y, xb[1], vB);
        vB = fma2(q1.x, xb[2], vB);
        vB = fma2(q1.y, xb[3], vB);
        vB = fma2(q2.x, xb[4], vB);
        vB = fma2(q2.y, xb[5], vB);
        vB = fma2(q3.x, xb[6], vB);
        vB = fma2(q3.y, xb[7], vB);

        if (flagv != 0.0f) {
            // Slow path: v += sig(a1 + Pz@x) * (-dt*v0[h])  (exact general case)
            const float* zrow = dynsm + PZ_BASE + h * CROW;
            ulonglong2 z0 = *(const ulonglong2*)(zrow);
            ulonglong2 z1 = *(const ulonglong2*)(zrow + 4);
            ulonglong2 z2 = *(const ulonglong2*)(zrow + 8);
            ulonglong2 z3 = *(const ulonglong2*)(zrow + 12);
            u64 a1d = *(const u64*)(zrow + 16);

            u64 aA = fma2(z0.x, xa[0], a1d);
            aA = fma2(z0.y, xa[1], aA); aA = fma2(z1.x, xa[2], aA);
            aA = fma2(z1.y, xa[3], aA); aA = fma2(z2.x, xa[4], aA);
            aA = fma2(z2.y, xa[5], aA); aA = fma2(z3.x, xa[6], aA);
            aA = fma2(z3.y, xa[7], aA);
            u64 aB = fma2(z0.x, xb[0], a1d);
            aB = fma2(z0.y, xb[1], aB); aB = fma2(z1.x, xb[2], aB);
            aB = fma2(z1.y, xb[3], aB); aB = fma2(z2.x, xb[4], aB);
            aB = fma2(z2.y, xb[5], aB); aB = fma2(z3.x, xb[6], aB);
            aB = fma2(z3.y, xb[7], aB);

            float zm = dynsm[ZM_BASE + 2 * h];
            float2 fa = u2f(aA), va = u2f(vA);
            va.x = fmaf(zm, 1.0f / (1.0f + __expf(-fa.x)), va.x);
            va.y = fmaf(zm, 1.0f / (1.0f + __expf(-fa.y)), va.y);
            vA = f2u(va.x, va.y);
            float2 fb = u2f(aB), vb = u2f(vB);
            vb.x = fmaf(zm, 1.0f / (1.0f + __expf(-fb.x)), vb.x);
            vb.y = fmaf(zm, 1.0f / (1.0f + __expf(-fb.y)), vb.y);
            vB = f2u(vb.x, vb.y);
        }

        // Stage into smem: pair p holds rows (2p, 2p+1) packed as f32x2 per h.
        *(u64*)(dynsm + t * SPAIR + 2 * h)           = vA;
        *(u64*)(dynsm + (256 + t) * SPAIR + 2 * h)   = vB;
    }
    __syncthreads();

    // Coalesced writeout: block owns flat float4 range [blockIdx*6144, +6144).
    const unsigned outTotF4 = (unsigned)B * 6u;
    const unsigned blockF4  = (unsigned)blockIdx.x * 6144u;
    float4* out4 = (float4*)out;
    #pragma unroll
    for (int k = 0; k < 24; ++k) {
        unsigned g = (unsigned)(k * 256 + t);
        if (blockF4 + g < outTotF4) {
            unsigned r  = g / 6u;                    // row within block
            unsigned h0 = (g - r * 6u) * 4u;         // starting h
            const float* pp = dynsm + (r >> 1) * SPAIR + (r & 1u) + 2u * h0;
            float4 v;
            v.x = pp[0]; v.y = pp[2]; v.z = pp[4]; v.w = pp[6];
            out4[blockF4 + g] = v;
        }
    }
}

// ---------------------------------------------------------------------------
extern "C" void kernel_launch(void* const* d_in, const int* in_sizes, int n_in,
                              void* d_out, int out_size) {
    const float* x  = (const float*)d_in[0];
    const float* W  = (const float*)d_in[1];
    const float* P  = (const float*)d_in[2];
    const float* bv = (const float*)d_in[3];
    const float* bz = (const float*)d_in[4];
    const float* e  = (const float*)d_in[5];
    const float* ep = (const float*)d_in[6];
    const float* cx = (const float*)d_in[7];
    const float* cu = (const float*)d_in[8];
    const float* cU = (const float*)d_in[9];
    const float* v0 = (const float*)d_in[10];
    const float* X0 = (const float*)d_in[11];
    const float* U0 = (const float*)d_in[12];

    const int B = in_sizes[0] / 8;
    const int nb = (B + 1023) / 1024;

    cudaFuncSetAttribute(cb_fused, cudaFuncAttributeMaxDynamicSharedMemorySize, SMEM_BYTES);
    if (nb > 0)
        cb_fused<<<nb, TPB, SMEM_BYTES>>>(x, (float*)d_out, B,
                                          W, P, bv, bz, e, ep, cx, cu, cU, v0, X0, U0);
}

// round 3
// speedup vs baseline: 1.1464x; 1.1447x over previous
#include <cuda_runtime.h>

#define TPB   256
#define RPB   512                        // rows per block (2 per thread)
#define SROW  25                         // staging row stride in words (odd -> conflict-free STS)
#define STAGE_W   (RPB * SROW)           // 12800 words
#define PD_BASE   STAGE_W                // 24 rows x 12 words: [8 x 0.1*P, c0, pad3]
#define PZ_BASE   (PD_BASE + 24 * 12)    // 24 rows x 12 words: [8 x pe*sp(P), a1, zm, pad2]
#define MISC_OFS  (PZ_BASE + 24 * 12)    // [0] = flag
#define SMEM_W    (MISC_OFS + 8)
#define SMEM_BYTES (SMEM_W * 4)          // 53,568 B -> 4 blocks/SM

__device__ __forceinline__ float sp_f(float x) {      // accurate softplus
    return fmaxf(x, 0.0f) + log1pf(expf(-fabsf(x)));
}
__device__ __forceinline__ float sig_f(float x) {
    return 1.0f / (1.0f + expf(-x));
}

// ---------------------------------------------------------------------------
// Per-block prologue: batch-invariant math, parallel over threads, no serial
// chains. Scratch aliases the staging region (written only after last sync).
// ---------------------------------------------------------------------------
__device__ __forceinline__ void block_prologue(
    float* sm,
    const float* __restrict__ W,  const float* __restrict__ P,
    const float* __restrict__ bv, const float* __restrict__ bz,
    const float* __restrict__ e,  const float* __restrict__ ep,
    const float* __restrict__ cx, const float* __restrict__ cu,
    const float* __restrict__ cU, const float* __restrict__ v0,
    const float* __restrict__ X0, const float* __restrict__ U0)
{
    const int t = threadIdx.x;
    float* rS  = sm;            // 24
    float* wS  = sm + 24;       // 24
    float* pkr = sm + 48;       // 24*8
    float* pwr = sm + 240;      // 24*8

    if (t < 24) {
        float v0v = v0[t];
        float rv  = sig_f(v0v);
        rS[t] = rv;
        float zx = 0.001f + 0.099f * sig_f(cx[t]);
        float X  = zx + (1.0f - zx) * X0[t] - U0[t] * X0[t] * rv;   // delta_t = 1
        float zu   = 0.001f + 0.099f * sig_f(cu[t]);
        float Ucap = 0.9f * sig_f(cU[t]);
        float U = Ucap * zu + (1.0f - zu) * U0[t] + Ucap * (1.0f - U0[t]) * rv;
        U = fminf(fmaxf(U, Ucap), 1.0f);
        wS[t] = U * X * rv;
        sm[PZ_BASE + t * 12 + 9] = -0.1f * v0v;                     // zm
    }
    if (t == 0) {
        float f = 0.0f;
        #pragma unroll
        for (int j = 0; j < 24; ++j)
            if (v0[j] != 0.0f) f = 1.0f;
        sm[MISC_OFS] = f;
    }
    __syncthreads();

    if (t < 192) {
        const int row = t >> 3;                  // h = 0..23
        const int q   = t & 7;                   // 0..7
        float kr = 0.0f, wur = 0.0f;
        #pragma unroll
        for (int jj = 0; jj < 3; ++jj) {
            int j = q * 3 + jj;
            float Wv = W[row * 24 + j];
            kr  += sp_f(Wv) * rS[j];
            wur += Wv * wS[j];
        }
        pkr[row * 8 + q] = kr;
        pwr[row * 8 + q] = wur;
        float pe = sp_f(ep[0]);
        float Pv = P[row * 8 + q];               // P is (H, IN) row-major
        sm[PD_BASE + row * 12 + q] = 0.1f * Pv;
        sm[PZ_BASE + row * 12 + q] = pe * sp_f(Pv);
    }
    __syncthreads();

    if (t < 24) {
        float kr = 0.0f, wur = 0.0f;
        #pragma unroll
        for (int k = 0; k < 8; ++k) { kr += pkr[t * 8 + k]; wur += pwr[t * 8 + k]; }
        float ke = sp_f(e[0]);
        sm[PZ_BASE + t * 12 + 8] = ke * kr + bz[t];                  // a1
        sm[PD_BASE + t * 12 + 8] = v0[t] + 0.1f * (wur + bv[t]);     // c0
    }
    __syncthreads();
}

// ---------------------------------------------------------------------------
// Fused kernel: block covers 512 rows; thread t owns rows t and t+256.
// ---------------------------------------------------------------------------
__global__ void __launch_bounds__(TPB, 4)
cb_fused(const float* __restrict__ x, float* __restrict__ out, int B,
         const float* __restrict__ W,  const float* __restrict__ P,
         const float* __restrict__ bv, const float* __restrict__ bz,
         const float* __restrict__ e,  const float* __restrict__ ep,
         const float* __restrict__ cx, const float* __restrict__ cu,
         const float* __restrict__ cU, const float* __restrict__ v0,
         const float* __restrict__ X0, const float* __restrict__ U0)
{
    extern __shared__ float sm[];
    const int t = threadIdx.x;
    const int rowA = blockIdx.x * RPB + t;
    const int rowB = rowA + 256;

    // x loads first: their latency covers the prologue's parameter loads.
    float xa[8], xb[8];
    #pragma unroll
    for (int i = 0; i < 8; ++i) {
        const float* xi = x + (size_t)i * (size_t)B;
        xa[i] = (rowA < B) ? __ldcs(xi + rowA) : 0.0f;
        xb[i] = (rowB < B) ? __ldcs(xi + rowB) : 0.0f;
    }

    block_prologue(sm, W, P, bv, bz, e, ep, cx, cu, cU, v0, X0, U0);

    const bool slow = (sm[MISC_OFS] != 0.0f);

    #pragma unroll 6
    for (int h = 0; h < 24; ++h) {
        const float4* rp = (const float4*)(sm + PD_BASE + h * 12);
        float4 cA = rp[0];
        float4 cB = rp[1];
        float4 cC = rp[2];                 // cC.x = c0

        float va = cC.x, vb = cC.x;
        va = fmaf(cA.x, xa[0], va);  vb = fmaf(cA.x, xb[0], vb);
        va = fmaf(cA.y, xa[1], va);  vb = fmaf(cA.y, xb[1], vb);
        va = fmaf(cA.z, xa[2], va);  vb = fmaf(cA.z, xb[2], vb);
        va = fmaf(cA.w, xa[3], va);  vb = fmaf(cA.w, xb[3], vb);
        va = fmaf(cB.x, xa[4], va);  vb = fmaf(cB.x, xb[4], vb);
        va = fmaf(cB.y, xa[5], va);  vb = fmaf(cB.y, xb[5], vb);
        va = fmaf(cB.z, xa[6], va);  vb = fmaf(cB.z, xb[6], vb);
        va = fmaf(cB.w, xa[7], va);  vb = fmaf(cB.w, xb[7], vb);

        if (slow) {
            // General case (v0 != 0): v += sig(a1 + Pz@x) * (-dt*v0[h]).
            const float4* zp = (const float4*)(sm + PZ_BASE + h * 12);
            float4 zA = zp[0];
            float4 zB = zp[1];
            float4 zC = zp[2];             // zC.x = a1, zC.y = zm
            float aa = zC.x, ab = zC.x;
            aa = fmaf(zA.x, xa[0], aa);  ab = fmaf(zA.x, xb[0], ab);
            aa = fmaf(zA.y, xa[1], aa);  ab = fmaf(zA.y, xb[1], ab);
            aa = fmaf(zA.z, xa[2], aa);  ab = fmaf(zA.z, xb[2], ab);
            aa = fmaf(zA.w, xa[3], aa);  ab = fmaf(zA.w, xb[3], ab);
            aa = fmaf(zB.x, xa[4], aa);  ab = fmaf(zB.x, xb[4], ab);
            aa = fmaf(zB.y, xa[5], aa);  ab = fmaf(zB.y, xb[5], ab);
            aa = fmaf(zB.z, xa[6], aa);  ab = fmaf(zB.z, xb[6], ab);
            aa = fmaf(zB.w, xa[7], aa);  ab = fmaf(zB.w, xb[7], ab);
            va = fmaf(zC.y, 1.0f / (1.0f + __expf(-aa)), va);
            vb = fmaf(zC.y, 1.0f / (1.0f + __expf(-ab)), vb);
        }

        sm[t * SROW + h]         = va;     // stride 25: conflict-free
        sm[(t + 256) * SROW + h] = vb;
    }
    __syncthreads();

    // Coalesced writeout: block owns float4 range [blockIdx*3072, +3072).
    const unsigned totF4  = (unsigned)B * 6u;
    const unsigned baseF4 = (unsigned)blockIdx.x * 3072u;
    float4* out4 = (float4*)out;
    #pragma unroll
    for (int k = 0; k < 12; ++k) {
        unsigned g = (unsigned)(k * 256 + t);          // 0..3071
        if (baseF4 + g < totF4) {
            unsigned r = g / 6u;                       // row within block
            unsigned c = g - r * 6u;                   // float4 column
            const float* pp = sm + r * SROW + c * 4u;
            float4 o;
            o.x = pp[0]; o.y = pp[1]; o.z = pp[2]; o.w = pp[3];
            out4[baseF4 + g] = o;
        }
    }
}

// ---------------------------------------------------------------------------
extern "C" void kernel_launch(void* const* d_in, const int* in_sizes, int n_in,
                              void* d_out, int out_size) {
    const float* x  = (const float*)d_in[0];
    const float* W  = (const float*)d_in[1];
    const float* P  = (const float*)d_in[2];
    const float* bv = (const float*)d_in[3];
    const float* bz = (const float*)d_in[4];
    const float* e  = (const float*)d_in[5];
    const float* ep = (const float*)d_in[6];
    const float* cx = (const float*)d_in[7];
    const float* cu = (const float*)d_in[8];
    const float* cU = (const float*)d_in[9];
    const float* v0 = (const float*)d_in[10];
    const float* X0 = (const float*)d_in[11];
    const float* U0 = (const float*)d_in[12];

    const int B  = in_sizes[0] / 8;
    const int nb = (B + RPB - 1) / RPB;

    static int attr_set = 0;
    if (!attr_set) {
        cudaFuncSetAttribute(cb_fused, cudaFuncAttributeMaxDynamicSharedMemorySize, SMEM_BYTES);
        attr_set = 1;
    }
    if (nb > 0)
        cb_fused<<<nb, TPB, SMEM_BYTES>>>(x, (float*)d_out, B,
                                          W, P, bv, bz, e, ep, cx, cu, cU, v0, X0, U0);
}